// round 3
// baseline (speedup 1.0000x reference)
#include <cuda_runtime.h>
#include <cstdint>
#include <cstddef>

typedef unsigned long long ull;

#define T_TOK 131072
#define NCHUNK 74
#define REC_L ((T_TOK + NCHUNK - 1) / NCHUNK)   /* 1772 */
#define REC_W 96
#define NSEG 1024

// ---------------- scratch (__device__ globals; no allocations allowed) ----------
__device__ float d_pre [(size_t)T_TOK * 1024];   // pre-activations: fwd gates 0..511, bwd 512..1023
__device__ float d_hs  [(size_t)T_TOK * 256];    // [hf | hb] per token
__device__ float d_u   [(size_t)T_TOK * 256];    // tanh(x @ w_omega)
__device__ float d_att [T_TOK];                  // attention logits
__device__ float d_wcat[1024 * 256];             // [w_ih_f ; w_ih_b]
__device__ float d_bias1[1024];                  // b_ih+b_hh (both dirs)
__device__ float d_bias2[256];                   // zeros
__device__ float d_womT[256 * 256];              // w_omega transposed: [n][k]

// ---------------- helpers ------------------------------------------------------
__device__ __forceinline__ ull ffma2(ull a, ull b, ull c) {
    ull d;
    asm("fma.rn.f32x2 %0, %1, %2, %3;" : "=l"(d) : "l"(a), "l"(b), "l"(c));
    return d;
}
__device__ __forceinline__ ull fpack(float x, float y) {
    ull r; asm("mov.b64 %0, {%1, %2};" : "=l"(r) : "f"(x), "f"(y)); return r;
}
__device__ __forceinline__ float hsum2(ull a) {
    float x, y; asm("mov.b64 {%0, %1}, %2;" : "=f"(x), "=f"(y) : "l"(a));
    return x + y;
}
__device__ __forceinline__ float sigf(float x) {
    return 1.0f / (1.0f + __expf(-x));
}
__device__ __forceinline__ float tanh_fast(float x) {
    return 2.0f / (1.0f + __expf(-2.0f * x)) - 1.0f;
}

// ---------------- prep: pack weights/biases ------------------------------------
__global__ void k_prep(const float* __restrict__ wihf, const float* __restrict__ wihb,
                       const float* __restrict__ bihf, const float* __restrict__ bhhf,
                       const float* __restrict__ bihb, const float* __restrict__ bhhb,
                       const float* __restrict__ womega)
{
    int i = blockIdx.x * 256 + threadIdx.x;     // grid 512 -> 131072 threads
    d_wcat[i] = wihf[i];
    d_wcat[131072 + i] = wihb[i];
    if (i < 65536) {                            // womT[n][k] = w_omega[k][n]
        int n = i >> 8, k = i & 255;
        d_womT[i] = womega[k * 256 + n];
    }
    if (i < 512) {
        d_bias1[i]       = bihf[i] + bhhf[i];
        d_bias1[512 + i] = bihb[i] + bhhb[i];
    }
    if (i < 256) d_bias2[i] = 0.0f;
}

// ---------------- SGEMM: C[M,N] = A[M,256] @ B[N,256]^T (+bias, opt tanh) ------
// MODE 0: A=ext(sentence), B=d_wcat, C=d_pre (ldc 1024, +bias1)
// MODE 1: A=d_hs,          B=d_womT, C=d_u   (ldc 256,  tanh)
template <int MODE>
__global__ __launch_bounds__(256, 1) void k_gemm(const float* __restrict__ Aext)
{
    const float* __restrict__ A = (MODE == 0) ? Aext : d_hs;
    const float* __restrict__ B = (MODE == 0) ? d_wcat : d_womT;
    float* __restrict__ C       = (MODE == 0) ? d_pre : d_u;
    const int ldc               = (MODE == 0) ? 1024 : 256;
    const float* __restrict__ bias = (MODE == 0) ? d_bias1 : d_bias2;

    __shared__ ull As[2][8][130];
    __shared__ ull Bs[2][8][130];

    const int tid = threadIdx.x;
    const int tx = tid & 15, ty = tid >> 4;
    const int M0 = blockIdx.y * 128, N0 = blockIdx.x * 128;

    const int lm = tid >> 2;      // 0..63
    const int lk = tid & 3;       // float4 slot in k-tile (16 k)

    const float* Abase = A + (size_t)M0 * 256;
    const float* Bbase = B + (size_t)N0 * 256;

    float4 ra0, ra1, rb0, rb1;
    auto LD = [&](int kt) {
        int ko = kt * 16 + lk * 4;
        ra0 = *(const float4*)(Abase + (size_t)lm * 256 + ko);
        ra1 = *(const float4*)(Abase + (size_t)(lm + 64) * 256 + ko);
        rb0 = *(const float4*)(Bbase + (size_t)lm * 256 + ko);
        rb1 = *(const float4*)(Bbase + (size_t)(lm + 64) * 256 + ko);
    };
    auto ST = [&](int buf) {
        As[buf][lk * 2    ][lm]      = fpack(ra0.x, ra0.y);
        As[buf][lk * 2 + 1][lm]      = fpack(ra0.z, ra0.w);
        As[buf][lk * 2    ][lm + 64] = fpack(ra1.x, ra1.y);
        As[buf][lk * 2 + 1][lm + 64] = fpack(ra1.z, ra1.w);
        Bs[buf][lk * 2    ][lm]      = fpack(rb0.x, rb0.y);
        Bs[buf][lk * 2 + 1][lm]      = fpack(rb0.z, rb0.w);
        Bs[buf][lk * 2    ][lm + 64] = fpack(rb1.x, rb1.y);
        Bs[buf][lk * 2 + 1][lm + 64] = fpack(rb1.z, rb1.w);
    };

    ull acc[8][8];
#pragma unroll
    for (int i = 0; i < 8; i++)
#pragma unroll
        for (int j = 0; j < 8; j++) acc[i][j] = 0ull;

    LD(0); ST(0); __syncthreads();

    for (int kt = 0; kt < 16; kt++) {
        int cur = kt & 1;
        if (kt < 15) LD(kt + 1);
#pragma unroll
        for (int p = 0; p < 8; p++) {
            ull a2[8], b2[8];
#pragma unroll
            for (int ii = 0; ii < 8; ii++) a2[ii] = As[cur][p][ty * 8 + ii];
#pragma unroll
            for (int jj = 0; jj < 8; jj++) b2[jj] = Bs[cur][p][tx + 16 * jj];
#pragma unroll
            for (int ii = 0; ii < 8; ii++)
#pragma unroll
                for (int jj = 0; jj < 8; jj++)
                    acc[ii][jj] = ffma2(a2[ii], b2[jj], acc[ii][jj]);
        }
        if (kt < 15) {
            __syncthreads();
            ST(cur ^ 1);
            __syncthreads();
        }
    }

#pragma unroll
    for (int ii = 0; ii < 8; ii++) {
        int i = ty * 8 + ii;
        float* Crow = C + (size_t)(M0 + i) * ldc + N0;
#pragma unroll
        for (int jj = 0; jj < 8; jj++) {
            int j = tx + 16 * jj;
            float v = hsum2(acc[ii][jj]) + bias[N0 + j];
            if (MODE == 1) v = tanhf(v);
            Crow[j] = v;
        }
    }
}

// ---------------- recurrence: chunked-parallel BiLSTM --------------------------
// 148 blocks: 0..73 fwd chunks, 74..147 bwd chunks. 256 threads.
// Thread tid owns gate rows r0=2*tid, r1=2*tid+1 (global rows 0..511).
// w_hh row: k-pairs 0..47 in regs, 48..63 in smem.
__global__ __launch_bounds__(256, 1) void k_rec(const float* __restrict__ whhf,
                                                const float* __restrict__ whhb,
                                                const float* __restrict__ h0,
                                                const float* __restrict__ c0)
{
    extern __shared__ unsigned char sraw[];
    ull*   wsm = (ull*)sraw;                       // 32 slots x 256 ull = 64 KB
    float* gsm = (float*)(sraw + 65536);           // 512 floats
    float* hsm = (float*)(sraw + 65536 + 2048);    // 128 floats (16B aligned)

    const int tid = threadIdx.x;
    const int bx  = blockIdx.x;
    const int dir = bx / NCHUNK;                   // 0 fwd, 1 bwd
    const int cid = bx % NCHUNK;
    const float* __restrict__ whh = dir ? whhb : whhf;

    const int r0 = 2 * tid;

    // load weights
    ull wr0[48], wr1[48];
    const ull* w0 = (const ull*)(whh + (size_t)r0 * 128);
    const ull* w1 = (const ull*)(whh + (size_t)(r0 + 1) * 128);
#pragma unroll
    for (int p = 0; p < 48; p++) { wr0[p] = __ldg(w0 + p); wr1[p] = __ldg(w1 + p); }
#pragma unroll
    for (int p = 0; p < 16; p++) {
        wsm[(p * 2 + 0) * 256 + tid] = __ldg(w0 + 48 + p);
        wsm[(p * 2 + 1) * 256 + tid] = __ldg(w1 + 48 + p);
    }

    const int lo = cid * REC_L;
    const int hi = min(lo + REC_L, T_TOK);
    const bool exact = (dir == 0) ? (cid == 0) : (cid == NCHUNK - 1);

    float cst = 0.0f, hv = 0.0f;
    if (tid < 128) {
        if (exact) { hv = h0[dir * 128 + tid]; cst = c0[dir * 128 + tid]; }
        hsm[tid] = hv;
    }
    __syncthreads();

    int tbeg, nsteps;
    if (dir == 0) {
        tbeg = exact ? lo : max(lo - REC_W, 0);
        nsteps = hi - tbeg;
    } else {
        tbeg = exact ? (hi - 1) : min(hi - 1 + REC_W, T_TOK - 1);
        nsteps = tbeg - lo + 1;
    }
    const int tinc = (dir == 0) ? 1 : -1;
    const float* __restrict__ preb = d_pre + dir * 512;

    int t = tbeg;
    for (int s = 0; s < nsteps; s++, t += tinc) {
        float2 p2 = *(const float2*)(preb + (size_t)t * 1024 + r0);

        ull a0 = 0ull, a1 = 0ull;
        const ulonglong2* h2 = (const ulonglong2*)hsm;
#pragma unroll
        for (int q = 0; q < 24; q++) {               // register-resident k-pairs 0..47
            ulonglong2 hh = h2[q];
            a0 = ffma2(wr0[2 * q], hh.x, a0);
            a0 = ffma2(wr0[2 * q + 1], hh.y, a0);
            a1 = ffma2(wr1[2 * q], hh.x, a1);
            a1 = ffma2(wr1[2 * q + 1], hh.y, a1);
        }
#pragma unroll
        for (int q = 24; q < 32; q++) {              // smem-resident k-pairs 48..63
            ulonglong2 hh = h2[q];
            int p0 = (q - 24) * 2, p1 = p0 + 1;
            a0 = ffma2(wsm[(p0 * 2 + 0) * 256 + tid], hh.x, a0);
            a0 = ffma2(wsm[(p1 * 2 + 0) * 256 + tid], hh.y, a0);
            a1 = ffma2(wsm[(p0 * 2 + 1) * 256 + tid], hh.x, a1);
            a1 = ffma2(wsm[(p1 * 2 + 1) * 256 + tid], hh.y, a1);
        }
        gsm[r0]     = p2.x + hsum2(a0);
        gsm[r0 + 1] = p2.y + hsum2(a1);
        __syncthreads();

        if (tid < 128) {
            float gi = gsm[tid];
            float gf = gsm[128 + tid];
            float gg = gsm[256 + tid];
            float go = gsm[384 + tid];
            cst = sigf(gf) * cst + sigf(gi) * tanh_fast(gg);
            hv  = sigf(go) * tanh_fast(cst);
            hsm[tid] = hv;
            bool emit = (dir == 0) ? (t >= lo) : (t < hi);
            if (emit) d_hs[(size_t)t * 256 + dir * 128 + tid] = hv;
        }
        __syncthreads();
    }
}

// ---------------- attention logits: att[t] = tanh(u)[t,:] . u_omega ------------
__global__ void k_att(const float* __restrict__ uom)
{
    int token = blockIdx.x * 8 + (threadIdx.x >> 5);
    int lane  = threadIdx.x & 31;
    const float* ur = d_u + (size_t)token * 256;
    float4 a  = *(const float4*)(ur + lane * 4);
    float4 b  = *(const float4*)(ur + 128 + lane * 4);
    float4 wa = *(const float4*)(uom + lane * 4);
    float4 wb = *(const float4*)(uom + 128 + lane * 4);
    float v = a.x * wa.x + a.y * wa.y + a.z * wa.z + a.w * wa.w
            + b.x * wb.x + b.y * wb.y + b.z * wb.z + b.w * wb.w;
#pragma unroll
    for (int o = 16; o > 0; o >>= 1) v += __shfl_down_sync(0xffffffffu, v, o);
    if (lane == 0) d_att[token] = v;
}

// ---------------- segment softmax-pool + tag projection ------------------------
__global__ void k_seg(const int* __restrict__ mask, const float* __restrict__ wtag,
                      const float* __restrict__ btag, float* __restrict__ out)
{
    const int s = blockIdx.x;
    const int tid = threadIdx.x;
    const int lo = (s == 0) ? 0 : mask[s - 1];
    const int hi = (s == NSEG - 1) ? T_TOK : mask[s];

    __shared__ float red[256];
    __shared__ float ctx[256];

    // segment max
    float m = -1e30f;
    for (int t = lo + tid; t < hi; t += 256) m = fmaxf(m, d_att[t]);
    red[tid] = m; __syncthreads();
#pragma unroll
    for (int o = 128; o > 0; o >>= 1) {
        if (tid < o) red[tid] = fmaxf(red[tid], red[tid + o]);
        __syncthreads();
    }
    m = red[0]; __syncthreads();

    // segment sum of exp
    float z = 0.0f;
    for (int t = lo + tid; t < hi; t += 256) z += __expf(d_att[t] - m);
    red[tid] = z; __syncthreads();
#pragma unroll
    for (int o = 128; o > 0; o >>= 1) {
        if (tid < o) red[tid] += red[tid + o];
        __syncthreads();
    }
    z = red[0];
    float invz = (z > 0.0f) ? (1.0f / z) : 0.0f;

    // weighted context: thread owns feature dim tid
    float acc = 0.0f;
    for (int t = lo; t < hi; t++) {
        float w = __expf(d_att[t] - m) * invz;
        acc += w * d_hs[(size_t)t * 256 + tid];
    }
    ctx[tid] = acc; __syncthreads();

    // tag projection
    if (tid < 10) {
        float o = btag[tid];
        const float* wr = wtag + tid * 256;
#pragma unroll 8
        for (int d = 0; d < 256; d++) o += ctx[d] * wr[d];
        out[s * 10 + tid] = o;
    }
}

// ---------------- launch --------------------------------------------------------
extern "C" void kernel_launch(void* const* d_in, const int* in_sizes, int n_in,
                              void* d_out, int out_size)
{
    const float* sentence = (const float*)d_in[0];
    const float* h0       = (const float*)d_in[1];
    const float* c0       = (const float*)d_in[2];
    const float* w_ih_f   = (const float*)d_in[3];
    const float* w_hh_f   = (const float*)d_in[4];
    const float* b_ih_f   = (const float*)d_in[5];
    const float* b_hh_f   = (const float*)d_in[6];
    const float* w_ih_b   = (const float*)d_in[7];
    const float* w_hh_b   = (const float*)d_in[8];
    const float* b_ih_b   = (const float*)d_in[9];
    const float* b_hh_b   = (const float*)d_in[10];
    // d_in[11] = w_omega (used in prep), 12 = u_omega, 13 = w_tag, 14 = b_tag, 15 = doc_mask
    const float* w_omega  = (const float*)d_in[11];
    const float* u_omega  = (const float*)d_in[12];
    const float* w_tag    = (const float*)d_in[13];
    const float* b_tag    = (const float*)d_in[14];
    const int*   doc_mask = (const int*)d_in[15];
    float* out = (float*)d_out;

    (void)in_sizes; (void)n_in; (void)out_size;

    cudaFuncSetAttribute(k_rec, cudaFuncAttributeMaxDynamicSharedMemorySize, 68096);

    k_prep<<<512, 256>>>(w_ih_f, w_ih_b, b_ih_f, b_hh_f, b_ih_b, b_hh_b, w_omega);
    k_gemm<0><<<dim3(8, 1024), 256>>>(sentence);
    k_rec<<<148, 256, 68096>>>(w_hh_f, w_hh_b, h0, c0);
    k_gemm<1><<<dim3(2, 1024), 256>>>(nullptr);
    k_att<<<T_TOK / 8, 256>>>(u_omega);
    k_seg<<<NSEG, 256>>>(doc_mask, w_tag, b_tag, out);
}

// round 5
// speedup vs baseline: 1.1935x; 1.1935x over previous
#include <cuda_runtime.h>
#include <cuda_bf16.h>
#include <cstdint>
#include <cstddef>

typedef unsigned long long ull;

#define T_TOK 131072
#define NCHUNK 74
#define REC_L ((T_TOK + NCHUNK - 1) / NCHUNK)   /* 1772 */
#define REC_W 96
#define NSEG 1024

// ---------------- scratch (__device__ globals; no allocations allowed) ----------
__device__ float d_pre [(size_t)T_TOK * 1024];   // pre-activations: fwd gates 0..511, bwd 512..1023
__device__ float d_hs  [(size_t)T_TOK * 256];    // [hf | hb] per token
__device__ float d_u   [(size_t)T_TOK * 256];    // tanh(x @ w_omega)
__device__ float d_att [T_TOK];                  // attention logits
__device__ float d_wcat[1024 * 256];             // [w_ih_f ; w_ih_b]
__device__ float d_bias1[1024];                  // b_ih+b_hh (both dirs)
__device__ float d_womT[256 * 256];              // w_omega transposed: [n][k]

// ---------------- helpers ------------------------------------------------------
__device__ __forceinline__ ull ffma2(ull a, ull b, ull c) {
    ull d;
    asm("fma.rn.f32x2 %0, %1, %2, %3;" : "=l"(d) : "l"(a), "l"(b), "l"(c));
    return d;
}
__device__ __forceinline__ float hsum2(ull a) {
    float x, y; asm("mov.b64 {%0, %1}, %2;" : "=f"(x), "=f"(y) : "l"(a));
    return x + y;
}
__device__ __forceinline__ float sigf(float x) {
    return 1.0f / (1.0f + __expf(-x));
}
__device__ __forceinline__ float tanh_fast(float x) {
    return 2.0f / (1.0f + __expf(-2.0f * x)) - 1.0f;
}
__device__ __forceinline__ uint32_t cvta_sm(const void* p) {
    uint32_t a;
    asm("{ .reg .u64 t; cvta.to.shared.u64 t, %1; cvt.u32.u64 %0, t; }" : "=r"(a) : "l"(p));
    return a;
}
// pack two floats -> bf16x2 word, x in low half (== ascending k order)
__device__ __forceinline__ uint32_t bf2pack(float x, float y) {
    uint32_t w;
    asm("cvt.rn.bf16x2.f32 %0, %1, %2;" : "=r"(w) : "f"(y), "f"(x));
    return w;
}
__device__ __forceinline__ void ldsm4(uint32_t& r0, uint32_t& r1, uint32_t& r2, uint32_t& r3,
                                      uint32_t addr) {
    asm volatile("ldmatrix.sync.aligned.m8n8.x4.shared.b16 {%0,%1,%2,%3}, [%4];"
                 : "=r"(r0), "=r"(r1), "=r"(r2), "=r"(r3) : "r"(addr));
}
__device__ __forceinline__ void mma16816(float* d, const uint32_t* a, uint32_t b0, uint32_t b1) {
    asm volatile(
        "mma.sync.aligned.m16n8k16.row.col.f32.bf16.bf16.f32 "
        "{%0,%1,%2,%3}, {%4,%5,%6,%7}, {%8,%9}, {%0,%1,%2,%3};"
        : "+f"(d[0]), "+f"(d[1]), "+f"(d[2]), "+f"(d[3])
        : "r"(a[0]), "r"(a[1]), "r"(a[2]), "r"(a[3]), "r"(b0), "r"(b1));
}

// ---------------- prep: pack weights/biases ------------------------------------
__global__ void k_prep(const float* __restrict__ wihf, const float* __restrict__ wihb,
                       const float* __restrict__ bihf, const float* __restrict__ bhhf,
                       const float* __restrict__ bihb, const float* __restrict__ bhhb,
                       const float* __restrict__ womega)
{
    int i = blockIdx.x * 256 + threadIdx.x;     // grid 512 -> 131072 threads
    d_wcat[i] = wihf[i];
    d_wcat[131072 + i] = wihb[i];
    if (i < 65536) {                            // womT[n][k] = w_omega[k][n]
        int n = i >> 8, k = i & 255;
        d_womT[i] = womega[k * 256 + n];
    }
    if (i < 512) {
        d_bias1[i]       = bihf[i] + bhhf[i];
        d_bias1[512 + i] = bihb[i] + bhhb[i];
    }
}

// ---------------- split-bf16 tensor-core GEMM ----------------------------------
// C[M,N] = A[M,256] @ B[N,256]^T ; A,B fp32 row-major (K contiguous).
// Split each operand x = hi(bf16) + lo(bf16); D = Ah*Bh + Ah*Bl + Al*Bh (fp32 acc).
// CTA tile 128(M) x 64(N), full K=256 staged once. 8 warps: 2(m) x 4(n), warp 64x16.
// MODE 0: A=sentence, B=d_wcat, C=d_pre (ldc 1024, +bias1)
// MODE 1: A=d_hs,     B=d_womT, C=d_u   (ldc 256,  tanh)
#define RS 528                      /* smem row stride bytes (33*16 -> conflict-free LDSM) */
#define A_HI 0
#define A_LO (128 * RS)             /* 67584  */
#define B_HI (2 * 128 * RS)         /* 135168 */
#define B_LO (2 * 128 * RS + 64 * RS)
#define GSMEM (2 * 128 * RS + 2 * 64 * RS)   /* 202752 */

template <int MODE>
__global__ __launch_bounds__(256, 1) void k_gemm_tc(const float* __restrict__ Aext)
{
    extern __shared__ unsigned char sm[];
    const float* __restrict__ A = (MODE == 0) ? Aext : d_hs;
    const float* __restrict__ B = (MODE == 0) ? d_wcat : d_womT;

    const int tid = threadIdx.x;
    const int M0 = blockIdx.y * 128;
    const int N0 = blockIdx.x * 64;

    // ---- stage A (128 rows) and B (64 rows), converting fp32 -> bf16 hi/lo ----
    {
        const float4* Ag = (const float4*)(A + (size_t)M0 * 256);
#pragma unroll
        for (int i = 0; i < 32; i++) {
            int f = i * 256 + tid;            // flat float4 id: row*64 + c
            int row = f >> 6, c = f & 63;
            float4 v = Ag[(size_t)row * 64 + c];
            float hx = __bfloat162float(__float2bfloat16(v.x));
            float hy = __bfloat162float(__float2bfloat16(v.y));
            float hz = __bfloat162float(__float2bfloat16(v.z));
            float hw = __bfloat162float(__float2bfloat16(v.w));
            uint2 wh = make_uint2(bf2pack(hx, hy), bf2pack(hz, hw));
            uint2 wl = make_uint2(bf2pack(v.x - hx, v.y - hy), bf2pack(v.z - hz, v.w - hw));
            *(uint2*)(sm + A_HI + row * RS + c * 8) = wh;
            *(uint2*)(sm + A_LO + row * RS + c * 8) = wl;
        }
        const float4* Bg = (const float4*)(B + (size_t)N0 * 256);
#pragma unroll
        for (int i = 0; i < 16; i++) {
            int f = i * 256 + tid;
            int row = f >> 6, c = f & 63;
            float4 v = Bg[(size_t)row * 64 + c];
            float hx = __bfloat162float(__float2bfloat16(v.x));
            float hy = __bfloat162float(__float2bfloat16(v.y));
            float hz = __bfloat162float(__float2bfloat16(v.z));
            float hw = __bfloat162float(__float2bfloat16(v.w));
            uint2 wh = make_uint2(bf2pack(hx, hy), bf2pack(hz, hw));
            uint2 wl = make_uint2(bf2pack(v.x - hx, v.y - hy), bf2pack(v.z - hz, v.w - hw));
            *(uint2*)(sm + B_HI + row * RS + c * 8) = wh;
            *(uint2*)(sm + B_LO + row * RS + c * 8) = wl;
        }
    }
    __syncthreads();

    const int lane = tid & 31, wid = tid >> 5;
    const int wm = wid & 1;          // m half (64 rows)
    const int wn = wid >> 1;         // n quarter (16 cols)
    const uint32_t smb = cvta_sm(sm);

    // per-lane LDSM base addresses (k-step adds ks*32 bytes)
    uint32_t a_hi_ad[4], a_lo_ad[4];
    {
        int ar = wm * 64 + (lane & 15);
        uint32_t ch = (uint32_t)(lane >> 4) * 16;
#pragma unroll
        for (int mi = 0; mi < 4; mi++) {
            uint32_t off = (uint32_t)(ar + mi * 16) * RS + ch;
            a_hi_ad[mi] = smb + A_HI + off;
            a_lo_ad[mi] = smb + A_LO + off;
        }
    }
    uint32_t b_hi_ad, b_lo_ad;
    {
        int br = wn * 16 + ((lane >> 4) << 3) + (lane & 7);
        uint32_t off = (uint32_t)br * RS + ((lane >> 3) & 1) * 16;
        b_hi_ad = smb + B_HI + off;
        b_lo_ad = smb + B_LO + off;
    }

    float acc[4][2][4];
#pragma unroll
    for (int mi = 0; mi < 4; mi++)
#pragma unroll
        for (int ni = 0; ni < 2; ni++)
#pragma unroll
            for (int r = 0; r < 4; r++) acc[mi][ni][r] = 0.0f;

#pragma unroll
    for (int ks = 0; ks < 16; ks++) {
        uint32_t ko = ks * 32;
        uint32_t bh[4], bl[4];
        ldsm4(bh[0], bh[1], bh[2], bh[3], b_hi_ad + ko);
        ldsm4(bl[0], bl[1], bl[2], bl[3], b_lo_ad + ko);
#pragma unroll
        for (int mi = 0; mi < 4; mi++) {
            uint32_t ah[4], al[4];
            ldsm4(ah[0], ah[1], ah[2], ah[3], a_hi_ad[mi] + ko);
            ldsm4(al[0], al[1], al[2], al[3], a_lo_ad[mi] + ko);
#pragma unroll
            for (int ni = 0; ni < 2; ni++) {
                uint32_t p0 = bh[2 * ni], p1 = bh[2 * ni + 1];
                mma16816(acc[mi][ni], ah, p0, p1);                       // Ah*Bh
                mma16816(acc[mi][ni], ah, bl[2 * ni], bl[2 * ni + 1]);   // Ah*Bl
                mma16816(acc[mi][ni], al, p0, p1);                       // Al*Bh
            }
        }
    }

    // ---- epilogue ----
    float* __restrict__ C = (MODE == 0) ? d_pre : d_u;
    const int ldc = (MODE == 0) ? 1024 : 256;
#pragma unroll
    for (int mi = 0; mi < 4; mi++) {
#pragma unroll
        for (int ni = 0; ni < 2; ni++) {
            int r  = M0 + wm * 64 + mi * 16 + (lane >> 2);
            int cg = N0 + wn * 16 + ni * 8 + (lane & 3) * 2;
            float v0 = acc[mi][ni][0], v1 = acc[mi][ni][1];
            float v2 = acc[mi][ni][2], v3 = acc[mi][ni][3];
            if (MODE == 0) {
                float b0 = d_bias1[cg], b1 = d_bias1[cg + 1];
                v0 += b0; v1 += b1; v2 += b0; v3 += b1;
            } else {
                v0 = tanhf(v0); v1 = tanhf(v1); v2 = tanhf(v2); v3 = tanhf(v3);
            }
            *(float2*)(C + (size_t)r * ldc + cg)       = make_float2(v0, v1);
            *(float2*)(C + (size_t)(r + 8) * ldc + cg) = make_float2(v2, v3);
        }
    }
}

// ---------------- recurrence: chunked-parallel BiLSTM --------------------------
__global__ __launch_bounds__(256, 1) void k_rec(const float* __restrict__ whhf,
                                                const float* __restrict__ whhb,
                                                const float* __restrict__ h0,
                                                const float* __restrict__ c0)
{
    extern __shared__ unsigned char sraw[];
    ull*   wsm = (ull*)sraw;                       // 32 slots x 256 ull = 64 KB
    float* gsm = (float*)(sraw + 65536);           // 512 floats
    float* hsm = (float*)(sraw + 65536 + 2048);    // 128 floats (16B aligned)

    const int tid = threadIdx.x;
    const int bx  = blockIdx.x;
    const int dir = bx / NCHUNK;                   // 0 fwd, 1 bwd
    const int cid = bx % NCHUNK;
    const float* __restrict__ whh = dir ? whhb : whhf;

    const int r0 = 2 * tid;

    ull wr0[48], wr1[48];
    const ull* w0 = (const ull*)(whh + (size_t)r0 * 128);
    const ull* w1 = (const ull*)(whh + (size_t)(r0 + 1) * 128);
#pragma unroll
    for (int p = 0; p < 48; p++) { wr0[p] = __ldg(w0 + p); wr1[p] = __ldg(w1 + p); }
#pragma unroll
    for (int p = 0; p < 16; p++) {
        wsm[(p * 2 + 0) * 256 + tid] = __ldg(w0 + 48 + p);
        wsm[(p * 2 + 1) * 256 + tid] = __ldg(w1 + 48 + p);
    }

    const int lo = cid * REC_L;
    const int hi = min(lo + REC_L, T_TOK);
    const bool exact = (dir == 0) ? (cid == 0) : (cid == NCHUNK - 1);

    float cst = 0.0f, hv = 0.0f;
    if (tid < 128) {
        if (exact) { hv = h0[dir * 128 + tid]; cst = c0[dir * 128 + tid]; }
        hsm[tid] = hv;
    }
    __syncthreads();

    int tbeg, nsteps;
    if (dir == 0) {
        tbeg = exact ? lo : max(lo - REC_W, 0);
        nsteps = hi - tbeg;
    } else {
        tbeg = exact ? (hi - 1) : min(hi - 1 + REC_W, T_TOK - 1);
        nsteps = tbeg - lo + 1;
    }
    const int tinc = (dir == 0) ? 1 : -1;
    const float* __restrict__ preb = d_pre + dir * 512;

    int t = tbeg;
    for (int s = 0; s < nsteps; s++, t += tinc) {
        float2 p2 = *(const float2*)(preb + (size_t)t * 1024 + r0);

        ull a0 = 0ull, a1 = 0ull;
        const ulonglong2* h2 = (const ulonglong2*)hsm;
#pragma unroll
        for (int q = 0; q < 24; q++) {               // register-resident k-pairs 0..47
            ulonglong2 hh = h2[q];
            a0 = ffma2(wr0[2 * q], hh.x, a0);
            a0 = ffma2(wr0[2 * q + 1], hh.y, a0);
            a1 = ffma2(wr1[2 * q], hh.x, a1);
            a1 = ffma2(wr1[2 * q + 1], hh.y, a1);
        }
#pragma unroll
        for (int q = 24; q < 32; q++) {              // smem-resident k-pairs 48..63
            ulonglong2 hh = h2[q];
            int p0 = (q - 24) * 2, p1 = p0 + 1;
            a0 = ffma2(wsm[(p0 * 2 + 0) * 256 + tid], hh.x, a0);
            a0 = ffma2(wsm[(p1 * 2 + 0) * 256 + tid], hh.y, a0);
            a1 = ffma2(wsm[(p0 * 2 + 1) * 256 + tid], hh.x, a1);
            a1 = ffma2(wsm[(p1 * 2 + 1) * 256 + tid], hh.y, a1);
        }
        gsm[r0]     = p2.x + hsum2(a0);
        gsm[r0 + 1] = p2.y + hsum2(a1);
        __syncthreads();

        if (tid < 128) {
            float gi = gsm[tid];
            float gf = gsm[128 + tid];
            float gg = gsm[256 + tid];
            float go = gsm[384 + tid];
            cst = sigf(gf) * cst + sigf(gi) * tanh_fast(gg);
            hv  = sigf(go) * tanh_fast(cst);
            hsm[tid] = hv;
            bool emit = (dir == 0) ? (t >= lo) : (t < hi);
            if (emit) d_hs[(size_t)t * 256 + dir * 128 + tid] = hv;
        }
        __syncthreads();
    }
}

// ---------------- attention logits: att[t] = tanh(u)[t,:] . u_omega ------------
__global__ void k_att(const float* __restrict__ uom)
{
    int token = blockIdx.x * 8 + (threadIdx.x >> 5);
    int lane  = threadIdx.x & 31;
    const float* ur = d_u + (size_t)token * 256;
    float4 a  = *(const float4*)(ur + lane * 4);
    float4 b  = *(const float4*)(ur + 128 + lane * 4);
    float4 wa = *(const float4*)(uom + lane * 4);
    float4 wb = *(const float4*)(uom + 128 + lane * 4);
    float v = a.x * wa.x + a.y * wa.y + a.z * wa.z + a.w * wa.w
            + b.x * wb.x + b.y * wb.y + b.z * wb.z + b.w * wb.w;
#pragma unroll
    for (int o = 16; o > 0; o >>= 1) v += __shfl_down_sync(0xffffffffu, v, o);
    if (lane == 0) d_att[token] = v;
}

// ---------------- segment softmax-pool + tag projection ------------------------
__global__ void k_seg(const int* __restrict__ mask, const float* __restrict__ wtag,
                      const float* __restrict__ btag, float* __restrict__ out)
{
    const int s = blockIdx.x;
    const int tid = threadIdx.x;
    const int lo = (s == 0) ? 0 : mask[s - 1];
    const int hi = (s == NSEG - 1) ? T_TOK : mask[s];

    __shared__ float red[256];
    __shared__ float ctx[256];

    float m = -1e30f;
    for (int t = lo + tid; t < hi; t += 256) m = fmaxf(m, d_att[t]);
    red[tid] = m; __syncthreads();
#pragma unroll
    for (int o = 128; o > 0; o >>= 1) {
        if (tid < o) red[tid] = fmaxf(red[tid], red[tid + o]);
        __syncthreads();
    }
    m = red[0]; __syncthreads();

    float z = 0.0f;
    for (int t = lo + tid; t < hi; t += 256) z += __expf(d_att[t] - m);
    red[tid] = z; __syncthreads();
#pragma unroll
    for (int o = 128; o > 0; o >>= 1) {
        if (tid < o) red[tid] += red[tid + o];
        __syncthreads();
    }
    z = red[0];
    float invz = (z > 0.0f) ? (1.0f / z) : 0.0f;

    float acc = 0.0f;
    for (int t = lo; t < hi; t++) {
        float w = __expf(d_att[t] - m) * invz;
        acc += w * d_hs[(size_t)t * 256 + tid];
    }
    ctx[tid] = acc; __syncthreads();

    if (tid < 10) {
        float o = btag[tid];
        const float* wr = wtag + tid * 256;
#pragma unroll 8
        for (int d = 0; d < 256; d++) o += ctx[d] * wr[d];
        out[s * 10 + tid] = o;
    }
}

// ---------------- launch --------------------------------------------------------
extern "C" void kernel_launch(void* const* d_in, const int* in_sizes, int n_in,
                              void* d_out, int out_size)
{
    const float* sentence = (const float*)d_in[0];
    const float* h0       = (const float*)d_in[1];
    const float* c0       = (const float*)d_in[2];
    const float* w_ih_f   = (const float*)d_in[3];
    const float* w_hh_f   = (const float*)d_in[4];
    const float* b_ih_f   = (const float*)d_in[5];
    const float* b_hh_f   = (const float*)d_in[6];
    const float* w_ih_b   = (const float*)d_in[7];
    const float* w_hh_b   = (const float*)d_in[8];
    const float* b_ih_b   = (const float*)d_in[9];
    const float* b_hh_b   = (const float*)d_in[10];
    const float* w_omega  = (const float*)d_in[11];
    const float* u_omega  = (const float*)d_in[12];
    const float* w_tag    = (const float*)d_in[13];
    const float* b_tag    = (const float*)d_in[14];
    const int*   doc_mask = (const int*)d_in[15];
    float* out = (float*)d_out;

    (void)in_sizes; (void)n_in; (void)out_size;

    cudaFuncSetAttribute(k_rec, cudaFuncAttributeMaxDynamicSharedMemorySize, 68096);
    cudaFuncSetAttribute(k_gemm_tc<0>, cudaFuncAttributeMaxDynamicSharedMemorySize, GSMEM);
    cudaFuncSetAttribute(k_gemm_tc<1>, cudaFuncAttributeMaxDynamicSharedMemorySize, GSMEM);

    k_prep<<<512, 256>>>(w_ih_f, w_ih_b, b_ih_f, b_hh_f, b_ih_b, b_hh_b, w_omega);
    k_gemm_tc<0><<<dim3(16, 1024), 256, GSMEM>>>(sentence);
    k_rec<<<148, 256, 68096>>>(w_hh_f, w_hh_b, h0, c0);
    k_gemm_tc<1><<<dim3(4, 1024), 256, GSMEM>>>(nullptr);
    k_att<<<T_TOK / 8, 256>>>(u_omega);
    k_seg<<<NSEG, 256>>>(doc_mask, w_tag, b_tag, out);
}